// round 16
// baseline (speedup 1.0000x reference)
#include <cuda_runtime.h>
#include <cuda_bf16.h>

// ---------------------------------------------------------------------------
// DisableGateLSTM: B=64, T=512, E=256, H=512, C=4
// Phase 1: pre-GEMM into g_pre laid out [t][bg][rg][g][16j][16b] (4KB blocks)
// Phase 2: persistent recurrence, 128 CTAs = 32 rg x 4 bg.
//          h arrives as 32 x 1KB cp.async.bulk slices, each issued the moment
//          its producer's flag is observed (straggler only serializes 1KB).
//          pre (4KB) double-buffered via bulk.  Weights in registers.
// Phase 3: logits = (max_t h) @ fc_w^T + fc_b
// ---------------------------------------------------------------------------

#define T_SEQ 512
#define NB    64
#define NE    256
#define NH    512
#define NG    2048
#define RECUR_CTAS 128

typedef unsigned long long u64;

// g_pre[t][bg][rg][g][jj][bb] : block (t,bg,rg) = 4*16*16 floats = 4KB
static __device__ float g_pre[(size_t)T_SEQ * 4 * 32 * 4 * 16 * 16];
// g_h[buf][bg][j][bb] : per-(buf,bg) block = 512*16 floats = 32KB contiguous
static __device__ float g_h[2][4][NH][16];
static __device__ float g_hmax[NH * NB];                  // [j][b] (old layout)
static __device__ int   g_flags[RECUR_CTAS];              // [bg][rg] progress
static __device__ int   g_count;                          // epilogue barrier
static __device__ int   g_sense;

// ---------------- f32x2 helpers ----------------
static __device__ __forceinline__ u64 fma2(u64 a, u64 b, u64 c) {
    u64 d;
    asm("fma.rn.f32x2 %0, %1, %2, %3;" : "=l"(d) : "l"(a), "l"(b), "l"(c));
    return d;
}
static __device__ __forceinline__ u64 add2(u64 a, u64 b) {
    u64 d;
    asm("add.rn.f32x2 %0, %1, %2;" : "=l"(d) : "l"(a), "l"(b));
    return d;
}
static __device__ __forceinline__ u64 pkdup(float a) {
    u64 r; asm("mov.b64 %0, {%1, %1};" : "=l"(r) : "f"(a)); return r;
}
static __device__ __forceinline__ float2 upk2(u64 a) {
    float2 f;
    asm("mov.b64 {%0, %1}, %2;" : "=f"(f.x), "=f"(f.y) : "l"(a));
    return f;
}
static __device__ __forceinline__ float sigf(float x) {
    return 1.f / (1.f + __expf(-x));
}
static __device__ __forceinline__ float tanh_fast(float x) {
    return 2.f / (1.f + __expf(-2.f * x)) - 1.f;
}

// ---------------- mbarrier / bulk-copy helpers ----------------
static __device__ __forceinline__ unsigned smem_u32(const void* p) {
    return (unsigned)__cvta_generic_to_shared(p);
}
static __device__ __forceinline__ void mbar_init(unsigned mbar, unsigned cnt) {
    asm volatile("mbarrier.init.shared.b64 [%0], %1;" :: "r"(mbar), "r"(cnt) : "memory");
}
static __device__ __forceinline__ void mbar_expect_tx(unsigned mbar, unsigned bytes) {
    asm volatile("mbarrier.arrive.expect_tx.shared.b64 _, [%0], %1;"
                 :: "r"(mbar), "r"(bytes) : "memory");
}
static __device__ __forceinline__ void bulk_g2s(unsigned sdst, const void* gsrc,
                                                unsigned bytes, unsigned mbar) {
    asm volatile(
        "cp.async.bulk.shared::cta.global.mbarrier::complete_tx::bytes [%0], [%1], %2, [%3];"
        :: "r"(sdst), "l"(gsrc), "r"(bytes), "r"(mbar) : "memory");
}
static __device__ __forceinline__ void mbar_wait(unsigned mbar, int parity) {
    asm volatile(
        "{\n\t"
        ".reg .pred P;\n\t"
        "W_%=:\n\t"
        "mbarrier.try_wait.parity.acquire.cta.shared::cta.b64 P, [%0], %1;\n\t"
        "@!P bra W_%=;\n\t"
        "}"
        :: "r"(mbar), "r"(parity) : "memory");
}

// =====================================================================
// Phase 1: pre-GEMM (R11 body; epilogue writes [t][bg][rg][g][jj][bb])
// =====================================================================
__global__ void __launch_bounds__(256, 2) pre_gemm(
    const int* __restrict__ ids, const float* __restrict__ emb,
    const float* __restrict__ Wf, const float* __restrict__ bf,
    const float* __restrict__ Wi, const float* __restrict__ bi,
    const float* __restrict__ Wo, const float* __restrict__ bo,
    const float* __restrict__ Wc, const float* __restrict__ bc)
{
    __shared__ float As[2][16][256];   // [kk][2*j] duplicated pairs
    __shared__ float Bs[2][16][128];   // [kk][m]

    const int t  = threadIdx.x;
    const int gx = blockIdx.x;
    const int m0 = blockIdx.y * 128;
    const int tx = t & 15, ty = t >> 4;

    const float* W    = (gx < 4) ? Wf : (gx < 8) ? Wi : (gx < 12) ? Wo : Wc;
    const float* bias = (gx < 4) ? bf : (gx < 8) ? bi : (gx < 12) ? bo : bc;
    const int jg0 = (gx & 3) * 128;

    const int jA0 = t >> 2;
    const int jA1 = jA0 + 64;
    const int qA  = t & 3;
    const int ml0 = t >> 2;
    const int ml1 = ml0 + 64;
    const int mg0 = m0 + ml0, mg1 = m0 + ml1;
    const int id0 = ids[(mg0 & 63) * T_SEQ + (mg0 >> 6)];
    const int id1 = ids[(mg1 & 63) * T_SEQ + (mg1 >> 6)];

    u64 acc[8][4];
#pragma unroll
    for (int jj = 0; jj < 8; ++jj)
#pragma unroll
        for (int s = 0; s < 4; ++s) acc[jj][s] = 0ull;

    float4 a0, a1, b0v, b1v;
    {
        const int k0 = 0;
        a0  = *(const float4*)&W[(size_t)(jg0 + jA0) * 768 + 512 + k0 + qA * 4];
        a1  = *(const float4*)&W[(size_t)(jg0 + jA1) * 768 + 512 + k0 + qA * 4];
        b0v = *(const float4*)&emb[(size_t)id0 * NE + k0 + qA * 4];
        b1v = *(const float4*)&emb[(size_t)id1 * NE + k0 + qA * 4];
    }
    {
        const int st = 0;
        As[st][qA*4+0][2*jA0] = a0.x; As[st][qA*4+0][2*jA0+1] = a0.x;
        As[st][qA*4+1][2*jA0] = a0.y; As[st][qA*4+1][2*jA0+1] = a0.y;
        As[st][qA*4+2][2*jA0] = a0.z; As[st][qA*4+2][2*jA0+1] = a0.z;
        As[st][qA*4+3][2*jA0] = a0.w; As[st][qA*4+3][2*jA0+1] = a0.w;
        As[st][qA*4+0][2*jA1] = a1.x; As[st][qA*4+0][2*jA1+1] = a1.x;
        As[st][qA*4+1][2*jA1] = a1.y; As[st][qA*4+1][2*jA1+1] = a1.y;
        As[st][qA*4+2][2*jA1] = a1.z; As[st][qA*4+2][2*jA1+1] = a1.z;
        As[st][qA*4+3][2*jA1] = a1.w; As[st][qA*4+3][2*jA1+1] = a1.w;
        Bs[st][qA*4+0][ml0] = b0v.x; Bs[st][qA*4+1][ml0] = b0v.y;
        Bs[st][qA*4+2][ml0] = b0v.z; Bs[st][qA*4+3][ml0] = b0v.w;
        Bs[st][qA*4+0][ml1] = b1v.x; Bs[st][qA*4+1][ml1] = b1v.y;
        Bs[st][qA*4+2][ml1] = b1v.z; Bs[st][qA*4+3][ml1] = b1v.w;
    }
    __syncthreads();

    int st = 0;
    for (int c = 0; c < 16; ++c) {
        if (c < 15) {
            const int k0 = (c + 1) * 16;
            a0  = *(const float4*)&W[(size_t)(jg0 + jA0) * 768 + 512 + k0 + qA * 4];
            a1  = *(const float4*)&W[(size_t)(jg0 + jA1) * 768 + 512 + k0 + qA * 4];
            b0v = *(const float4*)&emb[(size_t)id0 * NE + k0 + qA * 4];
            b1v = *(const float4*)&emb[(size_t)id1 * NE + k0 + qA * 4];
        }
#pragma unroll 4
        for (int kk = 0; kk < 16; ++kk) {
            ulonglong2 A01 = *(const ulonglong2*)&As[st][kk][ty * 16 + 0];
            ulonglong2 A23 = *(const ulonglong2*)&As[st][kk][ty * 16 + 4];
            ulonglong2 A45 = *(const ulonglong2*)&As[st][kk][ty * 16 + 8];
            ulonglong2 A67 = *(const ulonglong2*)&As[st][kk][ty * 16 + 12];
            u64 af[8] = {A01.x, A01.y, A23.x, A23.y, A45.x, A45.y, A67.x, A67.y};
            u64 bfr[4];
#pragma unroll
            for (int s = 0; s < 4; ++s)
                bfr[s] = *(const u64*)&Bs[st][kk][tx * 2 + s * 32];
#pragma unroll
            for (int jj = 0; jj < 8; ++jj)
#pragma unroll
                for (int s = 0; s < 4; ++s)
                    acc[jj][s] = fma2(bfr[s], af[jj], acc[jj][s]);
        }
        if (c < 15) {
            const int sn = st ^ 1;
            As[sn][qA*4+0][2*jA0] = a0.x; As[sn][qA*4+0][2*jA0+1] = a0.x;
            As[sn][qA*4+1][2*jA0] = a0.y; As[sn][qA*4+1][2*jA0+1] = a0.y;
            As[sn][qA*4+2][2*jA0] = a0.z; As[sn][qA*4+2][2*jA0+1] = a0.z;
            As[sn][qA*4+3][2*jA0] = a0.w; As[sn][qA*4+3][2*jA0+1] = a0.w;
            As[sn][qA*4+0][2*jA1] = a1.x; As[sn][qA*4+0][2*jA1+1] = a1.x;
            As[sn][qA*4+1][2*jA1] = a1.y; As[sn][qA*4+1][2*jA1+1] = a1.y;
            As[sn][qA*4+2][2*jA1] = a1.z; As[sn][qA*4+2][2*jA1+1] = a1.z;
            As[sn][qA*4+3][2*jA1] = a1.w; As[sn][qA*4+3][2*jA1+1] = a1.w;
            Bs[sn][qA*4+0][ml0] = b0v.x; Bs[sn][qA*4+1][ml0] = b0v.y;
            Bs[sn][qA*4+2][ml0] = b0v.z; Bs[sn][qA*4+3][ml0] = b0v.w;
            Bs[sn][qA*4+0][ml1] = b1v.x; Bs[sn][qA*4+1][ml1] = b1v.y;
            Bs[sn][qA*4+2][ml1] = b1v.z; Bs[sn][qA*4+3][ml1] = b1v.w;
        }
        __syncthreads();
        st ^= 1;
    }

    // epilogue: write into [t][bg][rg][g][jj][bb] blocks
#pragma unroll
    for (int jj = 0; jj < 8; ++jj) {
        const int row = gx * 128 + ty * 8 + jj;   // 0..2047
        const int g   = row >> 9;
        const int jg  = row & 511;
        const int rg  = jg >> 4;
        const int j16 = jg & 15;
        const float bv = bias[(gx & 3) * 128 + ty * 8 + jj];
#pragma unroll
        for (int s = 0; s < 4; ++s) {
            float2 v = upk2(acc[jj][s]);
            v.x += bv; v.y += bv;
            const int m  = m0 + tx * 2 + s * 32;
            const int tt = m >> 6, b = m & 63;
            const int bg = b >> 4, bb = b & 15;
            const size_t off =
                ((((size_t)tt * 4 + bg) * 32 + rg) * 4 + g) * 256 + j16 * 16 + bb;
            *(float2*)&g_pre[off] = v;
        }
    }
}

// =====================================================================
// Phase 2: persistent recurrence.  128 CTAs x 256 threads.
// CTA(bid): rg = bid>>2 owns h-rows [16rg,16rg+16); bg = bid&3 owns
// batches [16bg,16bg+16).  Thread t: rw = t>>3 (2 gate rows), ks = t&7.
// h: 32 x 1KB bulk slices, thread t<32 polls producer t's flag and issues
// its slice immediately (mb_h armed for 32768 B in previous step's tail).
// =====================================================================
__global__ void __launch_bounds__(256, 1) lstm_recur(
    const float* __restrict__ Wf, const float* __restrict__ Wi,
    const float* __restrict__ Wo, const float* __restrict__ Wc)
{
    extern __shared__ char smem[];
    const unsigned mb_h  = smem_u32(smem + 0);
    const unsigned mb_p0 = smem_u32(smem + 8);
    const unsigned mb_p1 = smem_u32(smem + 16);
    const unsigned hs_s   = smem_u32(smem + 128);
    const unsigned pres_s = smem_u32(smem + 32896);
    const u64*   hs64 = (const u64*)(smem + 128);
    const float* pres = (const float*)(smem + 32896);
    u64*         red  = (u64*)(smem + 41088);          // 8*580 u64 = 37120 B

    const int t   = threadIdx.x;
    const int bid = blockIdx.x;
    const int rg  = bid >> 2;
    const int bg  = bid & 3;
    const int rw  = t >> 3;                  // 0..31: gate-row pair
    const int ks  = t & 7;                   // k-slice of 64
    const int jj  = t >> 3, bp = t & 7;      // combine mapping (t<128)

    // ---- load weights into registers (once) ----
    float wreg[2][64];
    {
        const int r0 = rw * 2;
        const int g  = r0 >> 4;
        const int jl = r0 & 15;
        const float* Wg = (g == 0) ? Wf : (g == 1) ? Wi : (g == 2) ? Wo : Wc;
#pragma unroll
        for (int rr = 0; rr < 2; ++rr) {
            const float* p = &Wg[(size_t)(rg * 16 + jl + rr) * 768 + ks * 64];
#pragma unroll
            for (int q = 0; q < 16; ++q) {
                float4 v = *(const float4*)(p + q * 4);
                wreg[rr][q * 4 + 0] = v.x; wreg[rr][q * 4 + 1] = v.y;
                wreg[rr][q * 4 + 2] = v.z; wreg[rr][q * 4 + 3] = v.w;
            }
        }
    }

    // rotated chunk offsets: thread (rw,ks) reads pair p=(ks+i)&7 of its rows
    int off8[8], p8[8];
#pragma unroll
    for (int i = 0; i < 8; ++i) {
        p8[i]   = (ks + i) & 7;
        off8[i] = ks * 512 + p8[i];          // (ks*64 rows)*8 u64 + pair
    }

    // ---- init mbarriers; arm h-barrier for step 0; prefetch pre[0] ----
    if (t == 0) {
        mbar_init(mb_h, 1);
        mbar_init(mb_p0, 1);
        mbar_init(mb_p1, 1);
    }
    __syncthreads();
    if (t == 0) {
        mbar_expect_tx(mb_h, 32768);         // step 0 slices
        mbar_expect_tx(mb_p0, 4096);
        bulk_g2s(pres_s, g_pre + (((size_t)0 * 4 + bg) * 32 + rg) * 1024, 4096, mb_p0);
    }

    // ---- zero own slice of h[0], publish flag = 1 ----
    if (t < 128) {
        *(float2*)&g_h[0][bg][rg * 16 + jj][2 * bp] = make_float2(0.f, 0.f);
        __threadfence();
    }
    __syncthreads();                         // also orders t0's arm before polls
    if (t == 0) ((volatile int*)g_flags)[bg * 32 + rg] = 1;

    float cva = 0.f, cvb = 0.f;
    float hma = -1e30f, hmb = -1e30f;
    int pre_par[2] = {0, 0};

    for (int step = 0; step < T_SEQ; ++step) {
        const int pb = step & 1;

        // ---- t0: issue pre[step+1] bulk (independent of flags) ----
        if (t == 0) {
            const int ns = (step + 1 < T_SEQ) ? step + 1 : T_SEQ - 1;
            const unsigned mbp = (pb ^ 1) ? mb_p1 : mb_p0;
            mbar_expect_tx(mbp, 4096);
            bulk_g2s(pres_s + (pb ^ 1) * 4096,
                     g_pre + (((size_t)ns * 4 + bg) * 32 + rg) * 1024, 4096, mbp);
        }

        // ---- sliced h fetch: thread t<32 polls producer t, issues 1KB ----
        if (t < 32) {
            volatile int* fl = g_flags + bg * 32;
            while (fl[t] < step + 1) { }
            bulk_g2s(hs_s + t * 1024, &g_h[step & 1][bg][t * 16][0], 1024, mb_h);
        }

        // ---- wait: all 32 slices landed ----
        mbar_wait(mb_h, step & 1);

        // ---- compute: 2 rows x 8 rotated b-pairs over k-slice of 64 ----
        u64 acc0[8], acc1[8];
#pragma unroll
        for (int i = 0; i < 8; ++i) { acc0[i] = 0ull; acc1[i] = 0ull; }

#pragma unroll
        for (int kk = 0; kk < 64; ++kk) {
            const u64 w0 = pkdup(wreg[0][kk]);
            const u64 w1 = pkdup(wreg[1][kk]);
#pragma unroll
            for (int i = 0; i < 8; ++i) {
                const u64 hv = hs64[off8[i] + kk * 8];
                acc0[i] = fma2(hv, w0, acc0[i]);
                acc1[i] = fma2(hv, w1, acc1[i]);
            }
        }

        // ---- store k-partials to rotated logical slots ----
        {
            const int rbase0 = ks * 580 + (rw * 2 + 0) * 9;
            const int rbase1 = ks * 580 + (rw * 2 + 1) * 9;
#pragma unroll
            for (int i = 0; i < 8; ++i) {
                red[rbase0 + p8[i]] = acc0[i];
                red[rbase1 + p8[i]] = acc1[i];
            }
        }

        // ---- wait pre[step] (combiners only; parity tracked by all) ----
        if (t < 128) {
            const unsigned mbp = pb ? mb_p1 : mb_p0;
            mbar_wait(mbp, pre_par[pb]);
        }
        pre_par[pb] ^= 1;
        __syncthreads();

        // ---- combine + pointwise cell (threads 0..127) ----
        if (t < 128) {
            float2 gs[4];
#pragma unroll
            for (int g = 0; g < 4; ++g) {
                const int rbase = (g * 16 + jj) * 9 + bp;
                u64 s0 = add2(red[0 * 580 + rbase], red[1 * 580 + rbase]);
                u64 s1 = add2(red[2 * 580 + rbase], red[3 * 580 + rbase]);
                u64 s2 = add2(red[4 * 580 + rbase], red[5 * 580 + rbase]);
                u64 s3 = add2(red[6 * 580 + rbase], red[7 * 580 + rbase]);
                u64 sum = add2(add2(s0, s1), add2(s2, s3));
                float2 v  = upk2(sum);
                float2 pv = *(const float2*)&pres[pb * 1024 + (g * 16 + jj) * 16 + 2 * bp];
                gs[g] = make_float2(v.x + pv.x, v.y + pv.y);
            }
            const float fa = sigf(gs[0].x), fb = sigf(gs[0].y);
            const float ia = sigf(gs[1].x), ib = sigf(gs[1].y);
            const float oa = sigf(gs[2].x), ob = sigf(gs[2].y);
            const float ga = tanh_fast(gs[3].x), gb = tanh_fast(gs[3].y);
            cva = fa * cva + ia * ga;
            cvb = fb * cvb + ib * gb;
            const float ha = oa * tanh_fast(cva);
            const float hb = ob * tanh_fast(cvb);
            hma = fmaxf(hma, ha);
            hmb = fmaxf(hmb, hb);
            *(float2*)&g_h[(step + 1) & 1][bg][rg * 16 + jj][2 * bp] =
                make_float2(ha, hb);
            __threadfence();
        }
        // ---- re-arm h barrier for next step (phase flipped long ago) ----
        if (t == 0 && step + 1 < T_SEQ) mbar_expect_tx(mb_h, 32768);
        __syncthreads();                     // arm visible before next polls
        if (t == 0) ((volatile int*)g_flags)[bg * 32 + rg] = step + 2;
    }

    // ---- drain the final outstanding pre bulk (into buf 0) ----
    if (t == 0) mbar_wait(mb_p0, pre_par[0]);

    // ---- epilogue: write hmax (old [j][b] layout) ----
    if (t < 128)
        *(float2*)&g_hmax[(rg * 16 + jj) * 64 + bg * 16 + 2 * bp] = make_float2(hma, hmb);

    // two centralized sense barriers (even count -> g_sense restored),
    // flag reset in between: no CTA can still be polling when reset lands.
    int sense = 0;
#pragma unroll
    for (int rep = 0; rep < 2; ++rep) {
        __threadfence();
        __syncthreads();
        if (t == 0) {
            sense ^= 1;
            if (atomicAdd(&g_count, 1) == RECUR_CTAS - 1) {
                *(volatile int*)&g_count = 0;
                __threadfence();
                *(volatile int*)&g_sense = sense;
            } else {
                while (*(volatile int*)&g_sense != sense) { }
            }
            __threadfence();
        }
        __syncthreads();
        if (rep == 0 && t == 0) g_flags[bg * 32 + rg] = 0;
    }
}

// =====================================================================
// Phase 3: logits[b][c] = fc_b[c] + sum_j hmax[j][b] * fc_w[c][j]
// =====================================================================
__global__ void fc_kernel(const float* __restrict__ fcw,
                          const float* __restrict__ fcb,
                          float* __restrict__ out)
{
    const int t = threadIdx.x;
    const int b = t & 63, c = t >> 6;
    float acc = 0.f;
#pragma unroll 8
    for (int j = 0; j < NH; ++j)
        acc += g_hmax[j * 64 + b] * fcw[c * NH + j];
    out[b * 4 + c] = acc + fcb[c];
}

// =====================================================================
extern "C" void kernel_launch(void* const* d_in, const int* in_sizes, int n_in,
                              void* d_out, int out_size)
{
    (void)in_sizes; (void)n_in; (void)out_size;
    const int*   ids = (const int*)  d_in[0];
    const float* emb = (const float*)d_in[1];
    const float* Wf  = (const float*)d_in[2];
    const float* bf  = (const float*)d_in[3];
    const float* Wi  = (const float*)d_in[4];
    const float* bi  = (const float*)d_in[5];
    const float* Wo  = (const float*)d_in[6];
    const float* bo  = (const float*)d_in[7];
    const float* Wc  = (const float*)d_in[8];
    const float* bc  = (const float*)d_in[9];
    const float* fcw = (const float*)d_in[10];
    const float* fcb = (const float*)d_in[11];
    float* out = (float*)d_out;

    // mbars 128 + hs 32768 + pres 8192 + red 37120 = 78208 B
    const int recur_smem = 78208;
    cudaFuncSetAttribute(lstm_recur, cudaFuncAttributeMaxDynamicSharedMemorySize, recur_smem);

    pre_gemm<<<dim3(16, 256), 256>>>(ids, emb, Wf, bf, Wi, bi, Wo, bo, Wc, bc);
    lstm_recur<<<RECUR_CTAS, 256, recur_smem>>>(Wf, Wi, Wo, Wc);
    fc_kernel<<<1, 256>>>(fcw, fcb, out);
}